// round 1
// baseline (speedup 1.0000x reference)
#include <cuda_runtime.h>
#include <math.h>

// Problem constants
#define NCH  64      // B*C = 8*8
#define NLEN 2048    // N
#define LW   128     // window L
#define KK   1921    // N - L + 1
#define DCOMP 4      // components
#define AP   129     // padded pitch for 128-wide smem matrices

// Scratch (device globals; no allocation allowed)
__device__ double g_G[NCH * LW * LW];     // 8 MB Gram matrices (fp64)
__device__ float  g_V4[NCH * DCOMP * LW]; // top-4 eigenvectors per channel

// ---------------------------------------------------------------------------
// Kernel 1: Gram matrix via correlations + Hankel diagonal recurrence (fp64)
// G[l,m] = sum_k x[k+l]x[k+m];  G[l+1,m+1] = G[l,m] - x[l]x[m] + x[K+l]x[K+m]
// ---------------------------------------------------------------------------
__global__ void gram_kernel(const float* __restrict__ x) {
    __shared__ float  xs[NLEN];
    __shared__ double cd[LW];
    int bc = blockIdx.x;
    const float* xp = x + bc * NLEN;
    for (int i = threadIdx.x; i < NLEN; i += blockDim.x) xs[i] = xp[i];
    __syncthreads();

    int m = threadIdx.x;  // 128 threads: first row G[0][m] = corr(x, x shifted by m)
    double acc = 0.0;
    for (int k = 0; k < KK; k++) acc += (double)xs[k] * (double)xs[k + m];
    cd[m] = acc;
    __syncthreads();

    // thread d walks diagonal (l, l+d)
    int dg = threadIdx.x;
    double g = cd[dg];
    double* Gp = g_G + (size_t)bc * LW * LW;
    Gp[dg] = g;            // G[0][dg]
    Gp[dg * LW] = g;       // G[dg][0]
    for (int l = 1; l < LW - dg; l++) {
        int mm = l + dg;
        g += -(double)xs[l - 1] * (double)xs[mm - 1]
             + (double)xs[KK + l - 1] * (double)xs[KK + mm - 1];
        Gp[l * LW + mm] = g;
        Gp[mm * LW + l] = g;
    }
}

// ---------------------------------------------------------------------------
// Kernel 2: parallel round-robin two-sided Jacobi eigensolver.
// A (fp64) and V (fp32) in dynamic smem. One CTA per channel.
// ---------------------------------------------------------------------------
__global__ void __launch_bounds__(256, 1) jacobi_kernel() {
    extern __shared__ char smraw[];
    double* A = (double*)smraw;                              // 128*129 doubles
    float*  V = (float*)(smraw + LW * AP * sizeof(double));  // 128*129 floats

    __shared__ int    sp[64], sq[64];
    __shared__ double sc[64], ss[64];
    __shared__ double red[256];
    __shared__ double sfro;
    __shared__ int    sstop;
    __shared__ int    sel[4];
    __shared__ double dvals[LW];

    int tid = threadIdx.x;
    int bc = blockIdx.x;
    const double* Gp = g_G + (size_t)bc * LW * LW;

    for (int i = tid; i < LW * LW; i += 256) {
        int r = i >> 7, c = i & 127;
        A[r * AP + c] = Gp[i];
        V[r * AP + c] = (r == c) ? 1.0f : 0.0f;
    }
    __syncthreads();

    // Frobenius norm^2 for the convergence threshold
    double f = 0.0;
    for (int i = tid; i < LW * LW; i += 256) {
        double v = A[(i >> 7) * AP + (i & 127)];
        f += v * v;
    }
    red[tid] = f;
    __syncthreads();
    for (int s2 = 128; s2 > 0; s2 >>= 1) {
        if (tid < s2) red[tid] += red[tid + s2];
        __syncthreads();
    }
    if (tid == 0) { sfro = red[0]; sstop = 0; }
    __syncthreads();

    for (int sweep = 0; sweep < 12 && !sstop; sweep++) {
        for (int r = 0; r < 127; r++) {
            // 64 disjoint pairs (round-robin tournament schedule)
            if (tid < 64) {
                int p, q;
                if (tid == 0) { p = 127; q = r; }
                else { p = (r + tid) % 127; q = (r + 127 - tid) % 127; }
                double app = A[p * AP + p];
                double aqq = A[q * AP + q];
                double apq = A[p * AP + q];
                double c = 1.0, s = 0.0;
                if (fabs(apq) > 0.0) {
                    double th = (aqq - app) / (2.0 * apq);
                    double t = ((th >= 0.0) ? 1.0 : -1.0) /
                               (fabs(th) + sqrt(1.0 + th * th));
                    c = 1.0 / sqrt(1.0 + t * t);
                    s = t * c;
                }
                sp[tid] = p; sq[tid] = q; sc[tid] = c; ss[tid] = s;
            }
            __syncthreads();

            // Row updates: A <- J^T A   (coalesced along columns j)
            for (int job = tid; job < 64 * 128; job += 256) {
                int pr = job >> 7, j = job & 127;
                int p = sp[pr], q = sq[pr];
                double c = sc[pr], s = ss[pr];
                double ap = A[p * AP + j], aq = A[q * AP + j];
                A[p * AP + j] = c * ap - s * aq;
                A[q * AP + j] = s * ap + c * aq;
            }
            __syncthreads();

            // Column updates: A <- A J, and V <- V J (disjoint arrays)
            for (int job = tid; job < 64 * 128; job += 256) {
                int pr = job >> 7, rr = job & 127;
                int p = sp[pr], q = sq[pr];
                double c = sc[pr], s = ss[pr];
                double ap = A[rr * AP + p], aq = A[rr * AP + q];
                A[rr * AP + p] = c * ap - s * aq;
                A[rr * AP + q] = s * ap + c * aq;
            }
            for (int job = tid; job < 64 * 128; job += 256) {
                int pr = job >> 7, rr = job & 127;
                int p = sp[pr], q = sq[pr];
                float c = (float)sc[pr], s = (float)ss[pr];
                float ap = V[rr * AP + p], aq = V[rr * AP + q];
                V[rr * AP + p] = c * ap - s * aq;
                V[rr * AP + q] = s * ap + c * aq;
            }
            __syncthreads();
        }

        // off-diagonal norm^2 -> early exit
        double o = 0.0;
        for (int i = tid; i < LW * LW; i += 256) {
            int rr = i >> 7, cc = i & 127;
            if (rr != cc) {
                double v = A[rr * AP + cc];
                o += v * v;
            }
        }
        red[tid] = o;
        __syncthreads();
        for (int s2 = 128; s2 > 0; s2 >>= 1) {
            if (tid < s2) red[tid] += red[tid + s2];
            __syncthreads();
        }
        if (tid == 0 && red[0] < sfro * 1e-26) sstop = 1;
        __syncthreads();
    }

    // Select top-4 eigenvalues (descending) and export their eigenvectors
    if (tid < 128) dvals[tid] = A[tid * AP + tid];
    __syncthreads();
    if (tid == 0) {
        for (int j = 0; j < 4; j++) {
            int bi = 0;
            double bv = -1e300;
            for (int i2 = 0; i2 < 128; i2++)
                if (dvals[i2] > bv) { bv = dvals[i2]; bi = i2; }
            sel[j] = bi;
            dvals[bi] = -1e300;
        }
    }
    __syncthreads();
    if (tid < 128) {
        for (int j = 0; j < 4; j++)
            g_V4[(bc * DCOMP + j) * LW + tid] = V[tid * AP + sel[j]];
    }
}

// ---------------------------------------------------------------------------
// Kernel 3: reconstruction. w = T v (length-K correlation), then anti-diagonal
// average = conv(w, v)[n] / count[n].
// ---------------------------------------------------------------------------
__global__ void recon_kernel(const float* __restrict__ x, float* __restrict__ out) {
    __shared__ float xs[NLEN];
    __shared__ float vv[LW];
    __shared__ float w[KK];
    int bc = blockIdx.x;
    int comp = blockIdx.y;
    const float* xp = x + bc * NLEN;
    for (int i = threadIdx.x; i < NLEN; i += 256) xs[i] = xp[i];
    if (threadIdx.x < LW)
        vv[threadIdx.x] = g_V4[(bc * DCOMP + comp) * LW + threadIdx.x];
    __syncthreads();

    for (int k = threadIdx.x; k < KK; k += 256) {
        float a = 0.0f;
#pragma unroll 8
        for (int l = 0; l < LW; l++) a += xs[k + l] * vv[l];
        w[k] = a;
    }
    __syncthreads();

    float* op = out + ((size_t)comp * NCH + bc) * NLEN;
    for (int n = threadIdx.x; n < NLEN; n += 256) {
        int lmin = (n > KK - 1) ? (n - (KK - 1)) : 0;
        int lmax = (n < LW - 1) ? n : (LW - 1);
        float a = 0.0f;
        for (int l = lmin; l <= lmax; l++) a += vv[l] * w[n - l];
        int cnt = min(min(n + 1, NLEN - n), LW);
        op[n] = a / (float)cnt;
    }
}

// ---------------------------------------------------------------------------
extern "C" void kernel_launch(void* const* d_in, const int* in_sizes, int n_in,
                              void* d_out, int out_size) {
    const float* x = (const float*)d_in[0];
    float* out = (float*)d_out;

    const int SMEMJ = LW * AP * (int)sizeof(double) + LW * AP * (int)sizeof(float); // 198144 B
    // Idempotent; also executed during the pre-capture correctness call so the
    // attribute is already set even if this is a no-op under capture.
    cudaFuncSetAttribute(jacobi_kernel, cudaFuncAttributeMaxDynamicSharedMemorySize, SMEMJ);

    gram_kernel<<<NCH, 128>>>(x);
    jacobi_kernel<<<NCH, 256, SMEMJ>>>();
    recon_kernel<<<dim3(NCH, DCOMP), 256>>>(x, out);
}

// round 2
// speedup vs baseline: 4.7452x; 4.7452x over previous
#include <cuda_runtime.h>
#include <math.h>

#define NCH   64
#define NLEN  2048
#define LW    128
#define KK    1921
#define DCOMP 4

#define MK    64     // Krylov dimension
#define APG   129    // fp32 G smem pitch
#define APQ   65     // Q/W smem pitch
#define APH   65     // H/Y smem pitch
#define NR    12     // refined subspace size
#define APR   13     // U12/W12 pitch (doubles)

__device__ double g_G[NCH * LW * LW];      // fp64 Gram matrices
__device__ float  g_V4[NCH * DCOMP * LW];  // top-4 eigenvectors per channel

// ---------------------------------------------------------------------------
__device__ __forceinline__ float bsum128f(float v, volatile float* r4) {
#pragma unroll
    for (int o = 16; o; o >>= 1) v += __shfl_xor_sync(0xffffffffu, v, o);
    if ((threadIdx.x & 31) == 0) r4[threadIdx.x >> 5] = v;
    __syncthreads();
    float s = r4[0] + r4[1] + r4[2] + r4[3];
    __syncthreads();
    return s;
}
__device__ __forceinline__ double bsum128d(double v, volatile double* r4) {
#pragma unroll
    for (int o = 16; o; o >>= 1) v += __shfl_xor_sync(0xffffffffu, v, o);
    if ((threadIdx.x & 31) == 0) r4[threadIdx.x >> 5] = v;
    __syncthreads();
    double s = r4[0] + r4[1] + r4[2] + r4[3];
    __syncthreads();
    return s;
}

// ---------------------------------------------------------------------------
// Kernel 1: Gram matrix (fp64). First row via correlations (4 indep chains),
// then the Hankel diagonal recurrence.
// ---------------------------------------------------------------------------
__global__ void gram_kernel(const float* __restrict__ x) {
    __shared__ float  xs[NLEN];
    __shared__ double cd[LW];
    int bc = blockIdx.x;
    const float* xp = x + bc * NLEN;
    for (int i = threadIdx.x; i < NLEN; i += blockDim.x) xs[i] = xp[i];
    __syncthreads();

    int m = threadIdx.x;
    double a0 = 0, a1 = 0, a2 = 0, a3 = 0;
    int k = 0;
    for (; k + 4 <= KK; k += 4) {
        a0 += (double)xs[k]     * (double)xs[k + m];
        a1 += (double)xs[k + 1] * (double)xs[k + 1 + m];
        a2 += (double)xs[k + 2] * (double)xs[k + 2 + m];
        a3 += (double)xs[k + 3] * (double)xs[k + 3 + m];
    }
    for (; k < KK; k++) a0 += (double)xs[k] * (double)xs[k + m];
    cd[m] = a0 + a1 + a2 + a3;
    __syncthreads();

    int dg = threadIdx.x;
    double g = cd[dg];
    double* Gp = g_G + (size_t)bc * LW * LW;
    Gp[dg] = g;
    Gp[dg * LW] = g;
    for (int l = 1; l < LW - dg; l++) {
        int mm = l + dg;
        g += -(double)xs[l - 1] * (double)xs[mm - 1]
             + (double)xs[KK + l - 1] * (double)xs[KK + mm - 1];
        Gp[l * LW + mm] = g;
        Gp[mm * LW + l] = g;
    }
}

// ---------------------------------------------------------------------------
// Kernel 2: Krylov (Arnoldi w/ CGS2 full reorth, fp32) + Rayleigh-Ritz
//           + Jacobi on 64x64 H + fp64 refinement on top-12 subspace.
// One CTA (128 threads) per channel.
// ---------------------------------------------------------------------------
__global__ void __launch_bounds__(128, 1) eigen_kernel() {
    extern __shared__ char smraw[];
    float*  G32 = (float*)smraw;            // 128*129
    float*  Q   = G32 + LW * APG;           // 128*65
    float*  W   = Q + LW * APQ;             // 128*65
    float*  H   = W + LW * APQ;             // 64*65
    float*  Y   = H + MK * APH;             // 64*65
    double* U12 = (double*)(Y + MK * APH);  // 128*13 doubles
    double* W12 = U12 + LW * APR;           // 128*13 doubles

    __shared__ float  u[LW];
    __shared__ float  cvec[MK];
    __shared__ float  r4f[4];
    __shared__ double r4d[4];
    __shared__ int    sp[32], sq[32];
    __shared__ float  sc[32], ss[32];
    __shared__ double dc6[6], ds6[6];
    __shared__ int    sel12[NR];
    __shared__ float  vals[MK];
    __shared__ double H12[NR * APR];
    __shared__ double Z12[NR * APR];
    __shared__ int    idx4[4];
    __shared__ float  sfro;
    __shared__ int    sstop;

    int tid = threadIdx.x;
    int bc = blockIdx.x;
    const double* Gd = g_G + (size_t)bc * LW * LW;

    // fp32 copy of G (pitch 129 -> conflict-free column access)
    for (int i = tid; i < LW * LW; i += 128)
        G32[(i >> 7) * APG + (i & 127)] = (float)Gd[i];
    __syncthreads();

    // ---- initial vector ----
    float q0 = 1.0f + 0.5f * __sinf(0.7f * (float)tid + 0.3f);
    float n2 = bsum128f(q0 * q0, r4f);
    Q[tid * APQ + 0] = q0 * rsqrtf(n2);
    __syncthreads();

    // ---- Arnoldi with CGS2 full reorthogonalization ----
    for (int j = 0; j < MK - 1; j++) {
        // u = G * Q[:,j]
        float a0 = 0, a1 = 0, a2 = 0, a3 = 0;
        const float* gr = &G32[tid * APG];
        for (int l = 0; l < LW; l += 4) {
            a0 += gr[l]     * Q[l * APQ + j];
            a1 += gr[l + 1] * Q[(l + 1) * APQ + j];
            a2 += gr[l + 2] * Q[(l + 2) * APQ + j];
            a3 += gr[l + 3] * Q[(l + 3) * APQ + j];
        }
        float uv = a0 + a1 + a2 + a3;
        u[tid] = uv;
        __syncthreads();
        float pre2 = bsum128f(uv * uv, r4f);

        bool done = false;
        for (int attempt = 0; attempt < 2 && !done; attempt++) {
            for (int pass = 0; pass < 2; pass++) {
                if (tid <= j) {
                    float s = 0;
                    for (int i = 0; i < LW; i++) s += Q[i * APQ + tid] * u[i];
                    cvec[tid] = s;
                }
                __syncthreads();
                float corr = 0;
                for (int t = 0; t <= j; t++) corr += Q[tid * APQ + t] * cvec[t];
                u[tid] -= corr;
                __syncthreads();
            }
            float b2 = bsum128f(u[tid] * u[tid], r4f);
            if (b2 > pre2 * 1e-10f || attempt == 1) {
                Q[tid * APQ + (j + 1)] = u[tid] * rsqrtf(fmaxf(b2, 1e-30f));
                done = true;
            } else {
                // breakdown guard: inject generic vector, re-orthogonalize
                u[tid] = __sinf(0.37f * (float)((tid + 1) * (j + 3)) + 0.11f);
                __syncthreads();
                pre2 = bsum128f(u[tid] * u[tid], r4f);
            }
        }
        __syncthreads();
    }

    // ---- W = G * Q (register-blocked: 2 halves of 32 accumulators) ----
    for (int half = 0; half < 2; half++) {
        float acc[32];
#pragma unroll
        for (int t = 0; t < 32; t++) acc[t] = 0.f;
        const float* gr = &G32[tid * APG];
        for (int l = 0; l < LW; l++) {
            float g = gr[l];
            const float* qr = &Q[l * APQ + half * 32];
#pragma unroll
            for (int t = 0; t < 32; t++) acc[t] += g * qr[t];
        }
#pragma unroll
        for (int t = 0; t < 32; t++) W[tid * APQ + half * 32 + t] = acc[t];
    }
    __syncthreads();

    // ---- H = Q^T W, symmetrized ----
    for (int job = tid; job < MK * MK; job += 128) {
        int a = job >> 6, b = job & 63;
        if (a <= b) {
            float s = 0;
            for (int i = 0; i < LW; i++) s += Q[i * APQ + a] * W[i * APQ + b];
            H[a * APH + b] = s;
            H[b * APH + a] = s;
        }
    }
    __syncthreads();

    // ---- Jacobi on H (fp32, fp64 rotation angles) ----
    for (int i = tid; i < MK * MK; i += 128) {
        int r = i >> 6, c = i & 63;
        Y[r * APH + c] = (r == c) ? 1.f : 0.f;
    }
    float ff = 0;
    for (int i = tid; i < MK * MK; i += 128) {
        float v = H[(i >> 6) * APH + (i & 63)];
        ff += v * v;
    }
    ff = bsum128f(ff, r4f);
    if (tid == 0) { sfro = ff; sstop = 0; }
    __syncthreads();

    for (int sweep = 0; sweep < 12 && !sstop; sweep++) {
        for (int r = 0; r < MK - 1; r++) {
            if (tid < 32) {
                int p, q;
                if (tid == 0) { p = 63; q = r; }
                else { p = (r + tid) % 63; q = (r + 63 - tid) % 63; }
                float app = H[p * APH + p], aqq = H[q * APH + q], apq = H[p * APH + q];
                double c = 1.0, s = 0.0;
                if (fabsf(apq) > 0.f) {
                    double th = ((double)aqq - (double)app) / (2.0 * (double)apq);
                    double t = ((th >= 0.0) ? 1.0 : -1.0) /
                               (fabs(th) + sqrt(1.0 + th * th));
                    c = 1.0 / sqrt(1.0 + t * t);
                    s = t * c;
                }
                sp[tid] = p; sq[tid] = q; sc[tid] = (float)c; ss[tid] = (float)s;
            }
            __syncthreads();
            for (int job = tid; job < 32 * MK; job += 128) {
                int pr = job >> 6, jj = job & 63;
                int p = sp[pr], q = sq[pr];
                float c = sc[pr], s = ss[pr];
                float ap = H[p * APH + jj], aq = H[q * APH + jj];
                H[p * APH + jj] = c * ap - s * aq;
                H[q * APH + jj] = s * ap + c * aq;
            }
            __syncthreads();
            for (int job = tid; job < 32 * MK; job += 128) {
                int pr = job >> 6, rr = job & 63;
                int p = sp[pr], q = sq[pr];
                float c = sc[pr], s = ss[pr];
                float ap = H[rr * APH + p], aq = H[rr * APH + q];
                H[rr * APH + p] = c * ap - s * aq;
                H[rr * APH + q] = s * ap + c * aq;
                float yp = Y[rr * APH + p], yq = Y[rr * APH + q];
                Y[rr * APH + p] = c * yp - s * yq;
                Y[rr * APH + q] = s * yp + c * yq;
            }
            __syncthreads();
        }
        float o = 0;
        for (int i = tid; i < MK * MK; i += 128) {
            int rr = i >> 6, cc = i & 63;
            if (rr != cc) { float v = H[rr * APH + cc]; o += v * v; }
        }
        o = bsum128f(o, r4f);
        if (tid == 0 && o < sfro * 1e-12f) sstop = 1;
        __syncthreads();
    }

    // ---- pick top-12 Ritz pairs ----
    if (tid < MK) vals[tid] = H[tid * APH + tid];
    __syncthreads();
    if (tid == 0) {
        for (int j = 0; j < NR; j++) {
            int bi = 0;
            float bv = -3e38f;
            for (int i = 0; i < MK; i++)
                if (vals[i] > bv) { bv = vals[i]; bi = i; }
            sel12[j] = bi;
            vals[bi] = -3e38f;
        }
    }
    __syncthreads();

    // ---- U12 = Q * Y[:, top12]  (lift to fp64) ----
    for (int j = 0; j < NR; j++) {
        float s = 0;
        for (int t = 0; t < MK; t++) s += Q[tid * APQ + t] * Y[t * APH + sel12[j]];
        U12[tid * APR + j] = (double)s;
    }
    __syncthreads();

    // ---- fp64 MGS orthonormalization of U12 ----
    for (int a = 0; a < NR; a++) {
        double va = U12[tid * APR + a];
        double nn = bsum128d(va * va, r4d);
        double inv = 1.0 / sqrt(nn);
        va *= inv;
        U12[tid * APR + a] = va;
        for (int b = a + 1; b < NR; b++) {
            double d = bsum128d(va * U12[tid * APR + b], r4d);
            U12[tid * APR + b] -= d * va;
        }
    }

    // ---- W12 = G(fp64, from global) * U12 ----
    {
        double acc[NR];
#pragma unroll
        for (int j2 = 0; j2 < NR; j2++) acc[j2] = 0.0;
        const double* gr = Gd + (size_t)tid * LW;
        for (int l = 0; l < LW; l++) {
            double g = gr[l];
#pragma unroll
            for (int j2 = 0; j2 < NR; j2++) acc[j2] += g * U12[l * APR + j2];
        }
#pragma unroll
        for (int j2 = 0; j2 < NR; j2++) W12[tid * APR + j2] = acc[j2];
    }
    __syncthreads();

    // ---- H12 = U12^T W12 (fp64) ----
    for (int e = tid; e < NR * NR; e += 128) {
        int a = e / NR, b = e % NR;
        double s = 0;
        for (int i = 0; i < LW; i++) s += U12[i * APR + a] * W12[i * APR + b];
        H12[a * APR + b] = s;
    }
    __syncthreads();
    if (tid == 0) {
        for (int a = 0; a < NR; a++)
            for (int b = a + 1; b < NR; b++) {
                double mv = 0.5 * (H12[a * APR + b] + H12[b * APR + a]);
                H12[a * APR + b] = mv;
                H12[b * APR + a] = mv;
            }
    }
    __syncthreads();

    // ---- 12x12 fp64 Jacobi (parallel tournament) ----
    for (int e = tid; e < NR * NR; e += 128) {
        int a = e / NR, b = e % NR;
        Z12[a * APR + b] = (a == b) ? 1.0 : 0.0;
    }
    __syncthreads();
    for (int sweep = 0; sweep < 10; sweep++) {
        for (int r = 0; r < NR - 1; r++) {
            if (tid < 6) {
                int p, q;
                if (tid == 0) { p = NR - 1; q = r; }
                else { p = (r + tid) % (NR - 1); q = (r + NR - 1 - tid) % (NR - 1); }
                double app = H12[p * APR + p], aqq = H12[q * APR + q], apq = H12[p * APR + q];
                double c = 1.0, s = 0.0;
                if (fabs(apq) > 0.0) {
                    double th = (aqq - app) / (2.0 * apq);
                    double t = ((th >= 0.0) ? 1.0 : -1.0) /
                               (fabs(th) + sqrt(1.0 + th * th));
                    c = 1.0 / sqrt(1.0 + t * t);
                    s = t * c;
                }
                sp[tid] = p; sq[tid] = q; dc6[tid] = c; ds6[tid] = s;
            }
            __syncthreads();
            if (tid < 6 * NR) {
                int pr = tid / NR, jj = tid % NR;
                int p = sp[pr], q = sq[pr];
                double c = dc6[pr], s = ds6[pr];
                double ap = H12[p * APR + jj], aq = H12[q * APR + jj];
                H12[p * APR + jj] = c * ap - s * aq;
                H12[q * APR + jj] = s * ap + c * aq;
            }
            __syncthreads();
            if (tid < 6 * NR) {
                int pr = tid / NR, rr = tid % NR;
                int p = sp[pr], q = sq[pr];
                double c = dc6[pr], s = ds6[pr];
                double ap = H12[rr * APR + p], aq = H12[rr * APR + q];
                H12[rr * APR + p] = c * ap - s * aq;
                H12[rr * APR + q] = s * ap + c * aq;
                double zp = Z12[rr * APR + p], zq = Z12[rr * APR + q];
                Z12[rr * APR + p] = c * zp - s * zq;
                Z12[rr * APR + q] = s * zp + c * zq;
            }
            __syncthreads();
        }
    }

    // ---- top-4 refined eigenpairs, project back ----
    if (tid == 0) {
        double ev[NR];
        for (int a = 0; a < NR; a++) ev[a] = H12[a * APR + a];
        for (int j = 0; j < 4; j++) {
            int bi = 0;
            double bv = -1e300;
            for (int a = 0; a < NR; a++)
                if (ev[a] > bv) { bv = ev[a]; bi = a; }
            idx4[j] = bi;
            ev[bi] = -1e300;
        }
    }
    __syncthreads();
    for (int j = 0; j < 4; j++) {
        double s = 0;
#pragma unroll
        for (int a = 0; a < NR; a++) s += U12[tid * APR + a] * Z12[a * APR + idx4[j]];
        g_V4[(bc * DCOMP + j) * LW + tid] = (float)s;
    }
}

// ---------------------------------------------------------------------------
// Kernel 3: reconstruction. w = T v, then anti-diagonal average via conv.
// ---------------------------------------------------------------------------
__global__ void recon_kernel(const float* __restrict__ x, float* __restrict__ out) {
    __shared__ float xs[NLEN];
    __shared__ float vv[LW];
    __shared__ float w[KK];
    int bc = blockIdx.x;
    int comp = blockIdx.y;
    const float* xp = x + bc * NLEN;
    for (int i = threadIdx.x; i < NLEN; i += 256) xs[i] = xp[i];
    if (threadIdx.x < LW)
        vv[threadIdx.x] = g_V4[(bc * DCOMP + comp) * LW + threadIdx.x];
    __syncthreads();

    for (int k = threadIdx.x; k < KK; k += 256) {
        float a = 0.0f;
#pragma unroll 8
        for (int l = 0; l < LW; l++) a += xs[k + l] * vv[l];
        w[k] = a;
    }
    __syncthreads();

    float* op = out + ((size_t)comp * NCH + bc) * NLEN;
    for (int n = threadIdx.x; n < NLEN; n += 256) {
        int lmin = (n > KK - 1) ? (n - (KK - 1)) : 0;
        int lmax = (n < LW - 1) ? n : (LW - 1);
        float a = 0.0f;
        for (int l = lmin; l <= lmax; l++) a += vv[l] * w[n - l];
        int cnt = min(min(n + 1, NLEN - n), LW);
        op[n] = a / (float)cnt;
    }
}

// ---------------------------------------------------------------------------
extern "C" void kernel_launch(void* const* d_in, const int* in_sizes, int n_in,
                              void* d_out, int out_size) {
    const float* x = (const float*)d_in[0];
    float* out = (float*)d_out;

    const int SMEME = (LW * APG + 2 * LW * APQ + 2 * MK * APH) * (int)sizeof(float)
                      + 2 * LW * APR * (int)sizeof(double);  // 192512 B
    cudaFuncSetAttribute(eigen_kernel, cudaFuncAttributeMaxDynamicSharedMemorySize, SMEME);

    gram_kernel<<<NCH, 128>>>(x);
    eigen_kernel<<<NCH, 128, SMEME>>>();
    recon_kernel<<<dim3(NCH, DCOMP), 256>>>(x, out);
}

// round 3
// speedup vs baseline: 8.4899x; 1.7892x over previous
#include <cuda_runtime.h>
#include <math.h>

#define NCH   64
#define NLEN  2048
#define LW    128
#define KK    1921
#define DCOMP 4

#define MK    64     // Krylov dimension
#define APG   129    // fp32 G smem pitch
#define APQ   65     // Q smem pitch
#define NR    16     // refined subspace size
#define APR   17     // U16/W16 pitch (doubles)

__device__ double g_G[NCH * LW * LW];      // fp64 Gram matrices
__device__ float  g_V4[NCH * DCOMP * LW];  // top-4 eigenvectors per channel

// ---------------------------------------------------------------------------
__device__ __forceinline__ float bsum128f(float v, volatile float* r4) {
#pragma unroll
    for (int o = 16; o; o >>= 1) v += __shfl_xor_sync(0xffffffffu, v, o);
    if ((threadIdx.x & 31) == 0) r4[threadIdx.x >> 5] = v;
    __syncthreads();
    float s = r4[0] + r4[1] + r4[2] + r4[3];
    __syncthreads();
    return s;
}
__device__ __forceinline__ double bsum128d(double v, volatile double* r4) {
#pragma unroll
    for (int o = 16; o; o >>= 1) v += __shfl_xor_sync(0xffffffffu, v, o);
    if ((threadIdx.x & 31) == 0) r4[threadIdx.x >> 5] = v;
    __syncthreads();
    double s = r4[0] + r4[1] + r4[2] + r4[3];
    __syncthreads();
    return s;
}

// ---------------------------------------------------------------------------
// Kernel 1: Gram matrix (fp64): correlations + Hankel diagonal recurrence.
// ---------------------------------------------------------------------------
__global__ void gram_kernel(const float* __restrict__ x) {
    __shared__ float  xs[NLEN];
    __shared__ double cd[LW];
    int bc = blockIdx.x;
    const float* xp = x + bc * NLEN;
    for (int i = threadIdx.x; i < NLEN; i += blockDim.x) xs[i] = xp[i];
    __syncthreads();

    int m = threadIdx.x;
    double a0 = 0, a1 = 0, a2 = 0, a3 = 0;
    int k = 0;
    for (; k + 4 <= KK; k += 4) {
        a0 += (double)xs[k]     * (double)xs[k + m];
        a1 += (double)xs[k + 1] * (double)xs[k + 1 + m];
        a2 += (double)xs[k + 2] * (double)xs[k + 2 + m];
        a3 += (double)xs[k + 3] * (double)xs[k + 3 + m];
    }
    for (; k < KK; k++) a0 += (double)xs[k] * (double)xs[k + m];
    cd[m] = a0 + a1 + a2 + a3;
    __syncthreads();

    int dg = threadIdx.x;
    double g = cd[dg];
    double* Gp = g_G + (size_t)bc * LW * LW;
    Gp[dg] = g;
    Gp[dg * LW] = g;
    for (int l = 1; l < LW - dg; l++) {
        int mm = l + dg;
        g += -(double)xs[l - 1] * (double)xs[mm - 1]
             + (double)xs[KK + l - 1] * (double)xs[KK + mm - 1];
        Gp[l * LW + mm] = g;
        Gp[mm * LW + l] = g;
    }
}

// ---------------------------------------------------------------------------
// Kernel 2: Lanczos (fp32, CGS2 full reorth) -> tridiagonal T ->
//           bisection + inverse iteration for top-16 -> fp64 RR refinement.
// One CTA (128 threads) per channel.
// ---------------------------------------------------------------------------
__global__ void __launch_bounds__(128, 1) eigen_kernel() {
    extern __shared__ char smraw[];
    float*  G32 = (float*)smraw;                 // 128*129 f32
    float*  Q   = G32 + LW * APG;                // 128*65  f32
    double* U16 = (double*)(Q + LW * APQ);       // 128*17  f64
    double* W16 = U16 + LW * APR;                // 128*17  f64

    __shared__ float  u[LW];
    __shared__ float  cvec[MK];
    __shared__ float  r4f[4];
    __shared__ double r4d[4];
    __shared__ double salpha[MK];
    __shared__ double sbeta[MK];       // sbeta[j] = beta_j (j=0..62)
    __shared__ double Ytr[NR][MK];     // tridiag eigenvectors
    __shared__ double cpw[NR][MK];     // Thomas workspace
    __shared__ double lam[NR];
    __shared__ double H16[NR * APR];
    __shared__ double Z16[NR * APR];
    __shared__ int    sp[8], sq[8];
    __shared__ double dc8[8], ds8[8];
    __shared__ int    idx4[4];

    int tid = threadIdx.x;
    int lane = tid & 31, wid = tid >> 5;
    int bc = blockIdx.x;
    const double* Gd = g_G + (size_t)bc * LW * LW;

    // fp32 copy of G
    for (int i = tid; i < LW * LW; i += 128)
        G32[(i >> 7) * APG + (i & 127)] = (float)Gd[i];
    __syncthreads();

    // ---- initial vector ----
    float q0 = 1.0f + 0.5f * __sinf(0.7f * (float)tid + 0.3f);
    float n2 = bsum128f(q0 * q0, r4f);
    Q[tid * APQ + 0] = q0 * rsqrtf(n2);
    __syncthreads();

    // ---- Lanczos with CGS2 full reorthogonalization ----
    for (int j = 0; j < MK; j++) {
        // u = G * Q[:,j]
        float a0 = 0, a1 = 0, a2 = 0, a3 = 0;
        const float* gr = &G32[tid * APG];
        for (int l = 0; l < LW; l += 4) {
            a0 += gr[l]     * Q[l * APQ + j];
            a1 += gr[l + 1] * Q[(l + 1) * APQ + j];
            a2 += gr[l + 2] * Q[(l + 2) * APQ + j];
            a3 += gr[l + 3] * Q[(l + 3) * APQ + j];
        }
        float uv = a0 + a1 + a2 + a3;
        u[tid] = uv;
        __syncthreads();

        // alpha_j = q_j . u
        float al = bsum128f(Q[tid * APQ + j] * uv, r4f);
        if (tid == 0) salpha[j] = (double)al;
        if (j == MK - 1) break;

        float pre2 = bsum128f(uv * uv, r4f);

        bool done = false;
        for (int attempt = 0; attempt < 2 && !done; attempt++) {
            for (int pass = 0; pass < 2; pass++) {
                // cvec[t] = Q[:,t] . u  (warp per column, shfl reduce)
                for (int t = wid; t <= j; t += 4) {
                    float s = 0;
#pragma unroll
                    for (int i = lane; i < LW; i += 32) s += Q[i * APQ + t] * u[i];
#pragma unroll
                    for (int o = 16; o; o >>= 1) s += __shfl_xor_sync(0xffffffffu, s, o);
                    if (lane == 0) cvec[t] = s;
                }
                __syncthreads();
                float corr = 0;
                for (int t = 0; t <= j; t++) corr += Q[tid * APQ + t] * cvec[t];
                u[tid] -= corr;
                __syncthreads();
            }
            float b2 = bsum128f(u[tid] * u[tid], r4f);
            if (b2 > pre2 * 1e-12f || attempt == 1) {
                float bn = sqrtf(fmaxf(b2, 1e-30f));
                if (tid == 0) sbeta[j] = (double)bn;
                Q[tid * APQ + (j + 1)] = u[tid] / bn;
                done = true;
            } else {
                u[tid] = __sinf(0.37f * (float)((tid + 1) * (j + 3)) + 0.11f);
                __syncthreads();
                pre2 = bsum128f(u[tid] * u[tid], r4f);
            }
        }
        __syncthreads();
    }
    __syncthreads();

    // ---- top-16 eigenpairs of tridiagonal T via bisection + inverse iter ----
    if (tid < NR) {
        // Gershgorin bounds
        double lo = 1e300, hi = -1e300, bmax = 0.0;
        for (int i = 0; i < MK; i++) {
            double bl = (i > 0) ? fabs(sbeta[i - 1]) : 0.0;
            double br = (i < MK - 1) ? fabs(sbeta[i]) : 0.0;
            double r = bl + br;
            lo = fmin(lo, salpha[i] - r);
            hi = fmax(hi, salpha[i] + r);
            bmax = fmax(bmax, fmax(fabs(salpha[i]), br));
        }
        double guard = bmax * 1e-14 + 1e-300;

        int p = MK - 1 - tid;  // ascending index of the tid-th largest
        for (int it = 0; it < 55; it++) {
            double mid = 0.5 * (lo + hi);
            // Sturm count: #eigenvalues < mid
            int cnt = 0;
            double d = 1.0;
            for (int i = 0; i < MK; i++) {
                double off = (i > 0) ? (sbeta[i - 1] * sbeta[i - 1]) / d : 0.0;
                d = salpha[i] - mid - off;
                if (d < 0.0) cnt++;
                if (fabs(d) < guard) d = -guard;
            }
            if (cnt <= p) lo = mid; else hi = mid;
        }
        double lv = 0.5 * (lo + hi);
        lam[tid] = lv;

        // inverse iteration: (T - lv I) z = b, 3 guarded-Thomas solves
        double* y = Ytr[tid];
        double* cp = cpw[tid];
        for (int i = 0; i < MK; i++)
            y[i] = (double)__sinf(0.613f * (float)((i + 2) * (tid + 5)) + 0.21f);
        for (int iter = 0; iter < 3; iter++) {
            // forward
            double d = salpha[0] - lv;
            if (fabs(d) < guard) d = (d >= 0) ? guard : -guard;
            cp[0] = sbeta[0] / d;
            double z0 = y[0] / d;
            y[0] = z0;
            for (int i = 1; i < MK; i++) {
                double m = salpha[i] - lv - sbeta[i - 1] * cp[i - 1];
                if (fabs(m) < guard) m = (m >= 0) ? guard : -guard;
                if (i < MK - 1) cp[i] = sbeta[i] / m;
                y[i] = (y[i] - sbeta[i - 1] * y[i - 1]) / m;
            }
            // back substitution
            for (int i = MK - 2; i >= 0; i--) y[i] -= cp[i] * y[i + 1];
            // normalize
            double nn = 0.0;
            for (int i = 0; i < MK; i++) nn += y[i] * y[i];
            double inv = 1.0 / sqrt(nn);
            for (int i = 0; i < MK; i++) y[i] *= inv;
        }
    }
    __syncthreads();

    // ---- lift: U16[:,t] = Q * y_t  (fp64 accumulate) ----
    for (int t = 0; t < NR; t++) {
        double s = 0.0;
        const float* qr = &Q[tid * APQ];
        for (int k = 0; k < MK; k++) s += (double)qr[k] * Ytr[t][k];
        U16[tid * APR + t] = s;
    }
    __syncthreads();

    // ---- fp64 MGS orthonormalization of U16 ----
    for (int a = 0; a < NR; a++) {
        double va = U16[tid * APR + a];
        double nn = bsum128d(va * va, r4d);
        double inv = 1.0 / sqrt(fmax(nn, 1e-300));
        va *= inv;
        U16[tid * APR + a] = va;
        for (int b = a + 1; b < NR; b++) {
            double d = bsum128d(va * U16[tid * APR + b], r4d);
            U16[tid * APR + b] -= d * va;
        }
    }

    // ---- W16 = G(fp64) * U16 ----
    {
        double acc[NR];
#pragma unroll
        for (int t = 0; t < NR; t++) acc[t] = 0.0;
        const double* gr = Gd + (size_t)tid * LW;
        for (int l = 0; l < LW; l++) {
            double g = gr[l];
            const double* ur = &U16[l * APR];
#pragma unroll
            for (int t = 0; t < NR; t++) acc[t] += g * ur[t];
        }
#pragma unroll
        for (int t = 0; t < NR; t++) W16[tid * APR + t] = acc[t];
    }
    __syncthreads();

    // ---- H16 = U16^T W16 (fp64), symmetrized ----
    for (int e = tid; e < NR * NR; e += 128) {
        int a = e >> 4, b = e & 15;
        if (a <= b) {
            double s = 0;
            for (int i = 0; i < LW; i++) s += U16[i * APR + a] * W16[i * APR + b];
            H16[a * APR + b] = s;
            H16[b * APR + a] = s;
        }
    }
    for (int e = tid; e < NR * NR; e += 128) {
        int a = e >> 4, b = e & 15;
        Z16[a * APR + b] = (a == b) ? 1.0 : 0.0;
    }
    __syncthreads();

    // ---- 16x16 fp64 Jacobi (nearly diagonal already: 4 fixed sweeps) ----
    for (int sweep = 0; sweep < 4; sweep++) {
        for (int r = 0; r < NR - 1; r++) {
            if (tid < 8) {
                int p, q;
                if (tid == 0) { p = NR - 1; q = r; }
                else { p = (r + tid) % (NR - 1); q = (r + NR - 1 - tid) % (NR - 1); }
                double app = H16[p * APR + p], aqq = H16[q * APR + q], apq = H16[p * APR + q];
                double c = 1.0, s = 0.0;
                if (fabs(apq) > 0.0) {
                    double th = (aqq - app) / (2.0 * apq);
                    double t = ((th >= 0.0) ? 1.0 : -1.0) /
                               (fabs(th) + sqrt(1.0 + th * th));
                    c = 1.0 / sqrt(1.0 + t * t);
                    s = t * c;
                }
                sp[tid] = p; sq[tid] = q; dc8[tid] = c; ds8[tid] = s;
            }
            __syncthreads();
            if (tid < 8 * NR) {
                int pr = tid >> 4, jj = tid & 15;
                int p = sp[pr], q = sq[pr];
                double c = dc8[pr], s = ds8[pr];
                double ap = H16[p * APR + jj], aq = H16[q * APR + jj];
                H16[p * APR + jj] = c * ap - s * aq;
                H16[q * APR + jj] = s * ap + c * aq;
            }
            __syncthreads();
            if (tid < 8 * NR) {
                int pr = tid >> 4, rr = tid & 15;
                int p = sp[pr], q = sq[pr];
                double c = dc8[pr], s = ds8[pr];
                double ap = H16[rr * APR + p], aq = H16[rr * APR + q];
                H16[rr * APR + p] = c * ap - s * aq;
                H16[rr * APR + q] = s * ap + c * aq;
                double zp = Z16[rr * APR + p], zq = Z16[rr * APR + q];
                Z16[rr * APR + p] = c * zp - s * zq;
                Z16[rr * APR + q] = s * zp + c * zq;
            }
            __syncthreads();
        }
    }

    // ---- top-4 refined eigenpairs, project back ----
    if (tid == 0) {
        double ev[NR];
        for (int a = 0; a < NR; a++) ev[a] = H16[a * APR + a];
        for (int j = 0; j < 4; j++) {
            int bi = 0;
            double bv = -1e300;
            for (int a = 0; a < NR; a++)
                if (ev[a] > bv) { bv = ev[a]; bi = a; }
            idx4[j] = bi;
            ev[bi] = -1e300;
        }
    }
    __syncthreads();
    for (int j = 0; j < 4; j++) {
        double s = 0;
#pragma unroll
        for (int a = 0; a < NR; a++) s += U16[tid * APR + a] * Z16[a * APR + idx4[j]];
        g_V4[(bc * DCOMP + j) * LW + tid] = (float)s;
    }
}

// ---------------------------------------------------------------------------
// Kernel 3: reconstruction. w = T v, then anti-diagonal average via conv.
// ---------------------------------------------------------------------------
__global__ void recon_kernel(const float* __restrict__ x, float* __restrict__ out) {
    __shared__ float xs[NLEN];
    __shared__ float vv[LW];
    __shared__ float w[KK];
    int bc = blockIdx.x;
    int comp = blockIdx.y;
    const float* xp = x + bc * NLEN;
    for (int i = threadIdx.x; i < NLEN; i += 256) xs[i] = xp[i];
    if (threadIdx.x < LW)
        vv[threadIdx.x] = g_V4[(bc * DCOMP + comp) * LW + threadIdx.x];
    __syncthreads();

    for (int k = threadIdx.x; k < KK; k += 256) {
        float a = 0.0f;
#pragma unroll 8
        for (int l = 0; l < LW; l++) a += xs[k + l] * vv[l];
        w[k] = a;
    }
    __syncthreads();

    float* op = out + ((size_t)comp * NCH + bc) * NLEN;
    for (int n = threadIdx.x; n < NLEN; n += 256) {
        int lmin = (n > KK - 1) ? (n - (KK - 1)) : 0;
        int lmax = (n < LW - 1) ? n : (LW - 1);
        float a = 0.0f;
        for (int l = lmin; l <= lmax; l++) a += vv[l] * w[n - l];
        int cnt = min(min(n + 1, NLEN - n), LW);
        op[n] = a / (float)cnt;
    }
}

// ---------------------------------------------------------------------------
extern "C" void kernel_launch(void* const* d_in, const int* in_sizes, int n_in,
                              void* d_out, int out_size) {
    const float* x = (const float*)d_in[0];
    float* out = (float*)d_out;

    const int SMEME = (LW * APG + LW * APQ) * (int)sizeof(float)
                      + 2 * LW * APR * (int)sizeof(double);  // 134144 B
    cudaFuncSetAttribute(eigen_kernel, cudaFuncAttributeMaxDynamicSharedMemorySize, SMEME);

    gram_kernel<<<NCH, 128>>>(x);
    eigen_kernel<<<NCH, 128, SMEME>>>();
    recon_kernel<<<dim3(NCH, DCOMP), 256>>>(x, out);
}

// round 4
// speedup vs baseline: 14.2828x; 1.6823x over previous
#include <cuda_runtime.h>
#include <math.h>

#define NCH   64
#define NLEN  2048
#define LW    128
#define KK    1921
#define DCOMP 4

#define MK    64     // Krylov dimension
#define APG   129    // fp32 G smem pitch
#define APQ   65     // Q smem pitch
#define NR    16     // refined subspace size
#define APR   17     // U16/W16 pitch (doubles)

__device__ double g_G[NCH * LW * LW];      // fp64 Gram matrices
__device__ float  g_V4[NCH * DCOMP * LW];  // top-4 eigenvectors per channel

// ---------------------------------------------------------------------------
__device__ __forceinline__ float bsum128f(float v, volatile float* r8) {
#pragma unroll
    for (int o = 16; o; o >>= 1) v += __shfl_xor_sync(0xffffffffu, v, o);
    if ((threadIdx.x & 31) == 0) r8[threadIdx.x >> 5] = v;
    __syncthreads();
    float s = r8[0] + r8[1] + r8[2] + r8[3];
    __syncthreads();
    return s;
}
// dual reduction: one barrier pair for two sums
__device__ __forceinline__ float2 bsum128f2(float a, float b, volatile float* r8) {
#pragma unroll
    for (int o = 16; o; o >>= 1) {
        a += __shfl_xor_sync(0xffffffffu, a, o);
        b += __shfl_xor_sync(0xffffffffu, b, o);
    }
    if ((threadIdx.x & 31) == 0) {
        r8[threadIdx.x >> 5] = a;
        r8[4 + (threadIdx.x >> 5)] = b;
    }
    __syncthreads();
    float2 out = make_float2(r8[0] + r8[1] + r8[2] + r8[3],
                             r8[4] + r8[5] + r8[6] + r8[7]);
    __syncthreads();
    return out;
}
__device__ __forceinline__ double bsum128d(double v, volatile double* r4) {
#pragma unroll
    for (int o = 16; o; o >>= 1) v += __shfl_xor_sync(0xffffffffu, v, o);
    if ((threadIdx.x & 31) == 0) r4[threadIdx.x >> 5] = v;
    __syncthreads();
    double s = r4[0] + r4[1] + r4[2] + r4[3];
    __syncthreads();
    return s;
}

// ---------------------------------------------------------------------------
// Kernel 1: Gram matrix (fp64). First row via correlations (8 indep chains),
// then the Hankel diagonal recurrence.
// ---------------------------------------------------------------------------
__global__ void gram_kernel(const float* __restrict__ x) {
    __shared__ float  xs[NLEN];
    __shared__ double cd[LW];
    int bc = blockIdx.x;
    const float* xp = x + bc * NLEN;
    for (int i = threadIdx.x; i < NLEN; i += blockDim.x) xs[i] = xp[i];
    __syncthreads();

    int m = threadIdx.x;
    double acc[8];
#pragma unroll
    for (int t = 0; t < 8; t++) acc[t] = 0.0;
    int k = 0;
    for (; k + 8 <= KK; k += 8) {
#pragma unroll
        for (int t = 0; t < 8; t++)
            acc[t] += (double)xs[k + t] * (double)xs[k + t + m];
    }
    for (; k < KK; k++) acc[0] += (double)xs[k] * (double)xs[k + m];
    cd[m] = ((acc[0] + acc[1]) + (acc[2] + acc[3]))
          + ((acc[4] + acc[5]) + (acc[6] + acc[7]));
    __syncthreads();

    int dg = threadIdx.x;
    double g = cd[dg];
    double* Gp = g_G + (size_t)bc * LW * LW;
    Gp[dg] = g;
    Gp[dg * LW] = g;
    for (int l = 1; l < LW - dg; l++) {
        int mm = l + dg;
        g += -(double)xs[l - 1] * (double)xs[mm - 1]
             + (double)xs[KK + l - 1] * (double)xs[KK + mm - 1];
        Gp[l * LW + mm] = g;
        Gp[mm * LW + l] = g;
    }
}

// ---------------------------------------------------------------------------
// Kernel 2: Lanczos (fp32, CGS2) -> tridiagonal T -> parallel fp32 bisection
//           + fp64 inverse iteration (top-16) -> fp64 RR refinement.
// One CTA (128 threads) per channel.
// ---------------------------------------------------------------------------
__global__ void __launch_bounds__(128, 1) eigen_kernel() {
    extern __shared__ char smraw[];
    float*  G32 = (float*)smraw;                 // 128*129 f32
    float*  Q   = G32 + LW * APG;                // 128*65  f32
    double* U16 = (double*)(Q + LW * APQ);       // 128*17  f64
    double* W16 = U16 + LW * APR;                // 128*17  f64

    __shared__ float  u[LW];
    __shared__ float  cvec[MK];
    __shared__ float  r8f[8];
    __shared__ double r4d[4];
    __shared__ double salpha[MK];
    __shared__ double sbeta[MK];
    __shared__ float  sa32[MK];
    __shared__ float  sb232[MK];
    __shared__ double Ytr[NR][MK];
    __shared__ double cpw[NR][MK];
    __shared__ double lam[NR];
    __shared__ double H16[NR * APR];
    __shared__ double Z16[NR * APR];
    __shared__ int    sp[8], sq[8];
    __shared__ double dc8[8], ds8[8];
    __shared__ int    idx4[4];

    int tid = threadIdx.x;
    int lane = tid & 31, wid = tid >> 5;
    int bc = blockIdx.x;
    const double* Gd = g_G + (size_t)bc * LW * LW;

    for (int i = tid; i < LW * LW; i += 128)
        G32[(i >> 7) * APG + (i & 127)] = (float)Gd[i];
    __syncthreads();

    // ---- initial vector ----
    float q0 = 1.0f + 0.5f * __sinf(0.7f * (float)tid + 0.3f);
    float n2 = bsum128f(q0 * q0, r8f);
    Q[tid * APQ + 0] = q0 * rsqrtf(n2);
    __syncthreads();

    // ---- Lanczos with CGS2 full reorthogonalization ----
    for (int j = 0; j < MK; j++) {
        float a0 = 0, a1 = 0, a2 = 0, a3 = 0;
        const float* gr = &G32[tid * APG];
        for (int l = 0; l < LW; l += 4) {
            a0 += gr[l]     * Q[l * APQ + j];
            a1 += gr[l + 1] * Q[(l + 1) * APQ + j];
            a2 += gr[l + 2] * Q[(l + 2) * APQ + j];
            a3 += gr[l + 3] * Q[(l + 3) * APQ + j];
        }
        float uv = (a0 + a1) + (a2 + a3);
        u[tid] = uv;
        __syncthreads();

        float2 an = bsum128f2(Q[tid * APQ + j] * uv, uv * uv, r8f);
        if (tid == 0) salpha[j] = (double)an.x;
        if (j == MK - 1) break;
        float pre2 = an.y;

        // two CGS passes
        for (int pass = 0; pass < 2; pass++) {
            for (int t = wid; t <= j; t += 4) {
                float s = 0;
#pragma unroll
                for (int i = lane; i < LW; i += 32) s += Q[i * APQ + t] * u[i];
#pragma unroll
                for (int o = 16; o; o >>= 1) s += __shfl_xor_sync(0xffffffffu, s, o);
                if (lane == 0) cvec[t] = s;
            }
            __syncthreads();
            float corr = 0;
            for (int t = 0; t <= j; t++) corr += Q[tid * APQ + t] * cvec[t];
            u[tid] -= corr;
            __syncthreads();
        }
        float b2 = bsum128f(u[tid] * u[tid], r8f);
        float bn = sqrtf(fmaxf(b2, pre2 * 1e-14f + 1e-30f));
        if (tid == 0) sbeta[j] = (double)bn;
        Q[tid * APQ + (j + 1)] = u[tid] / bn;
        __syncthreads();
    }
    __syncthreads();

    // fp32 copies of the tridiagonal for bisection
    if (tid < MK) sa32[tid] = (float)salpha[tid];
    if (tid < MK - 1) sb232[tid] = (float)(sbeta[tid] * sbeta[tid]);
    __syncthreads();

    // ---- parallel fp32 bisection: 8 threads per eigenvalue, 9-way split ----
    {
        int g = tid >> 3, sub = tid & 7;
        int p = MK - 1 - g;      // ascending index of g-th largest
        // Gershgorin bounds (fp32, per-thread)
        float lo = 3e38f, hi = -3e38f, bmax = 0.f;
        for (int i = 0; i < MK; i++) {
            float bl = (i > 0) ? sqrtf(sb232[i - 1]) : 0.f;
            float br = (i < MK - 1) ? sqrtf(sb232[i]) : 0.f;
            float r = bl + br;
            lo = fminf(lo, sa32[i] - r);
            hi = fmaxf(hi, sa32[i] + r);
            bmax = fmaxf(bmax, fmaxf(fabsf(sa32[i]), br));
        }
        float gguard = bmax * 1e-6f + 1e-30f;

        for (int round = 0; round < 8; round++) {
            float w = hi - lo;
            float mid = lo + w * (float)(sub + 1) * (1.0f / 9.0f);
            int cnt = 0;
            float d = 1.0f;
            for (int i = 0; i < MK; i++) {
                float off = (i > 0) ? __fdividef(sb232[i - 1], d) : 0.f;
                d = sa32[i] - mid - off;
                cnt += (d < 0.f);
                if (fabsf(d) < gguard) d = -gguard;
            }
            float clo = (cnt <= p) ? mid : lo;
            float chi = (cnt > p) ? mid : hi;
#pragma unroll
            for (int o = 4; o; o >>= 1) {
                clo = fmaxf(clo, __shfl_xor_sync(0xffffffffu, clo, o));
                chi = fminf(chi, __shfl_xor_sync(0xffffffffu, chi, o));
            }
            lo = clo;
            hi = chi;
        }
        if (sub == 0) lam[g] = 0.5 * ((double)lo + (double)hi);
    }
    __syncthreads();

    // ---- fp64 inverse iteration (guarded Thomas), 16 threads ----
    if (tid < NR) {
        double bmaxd = 0.0;
        for (int i = 0; i < MK; i++) {
            double br = (i < MK - 1) ? fabs(sbeta[i]) : 0.0;
            bmaxd = fmax(bmaxd, fmax(fabs(salpha[i]), br));
        }
        double guard = bmaxd * 1e-13 + 1e-300;
        double lv = lam[tid];
        double* y = Ytr[tid];
        double* cp = cpw[tid];
        for (int i = 0; i < MK; i++)
            y[i] = (double)__sinf(0.613f * (float)((i + 2) * (tid + 5)) + 0.21f);
        for (int iter = 0; iter < 2; iter++) {
            double d = salpha[0] - lv;
            if (fabs(d) < guard) d = (d >= 0) ? guard : -guard;
            cp[0] = sbeta[0] / d;
            y[0] = y[0] / d;
            for (int i = 1; i < MK; i++) {
                double m = salpha[i] - lv - sbeta[i - 1] * cp[i - 1];
                if (fabs(m) < guard) m = (m >= 0) ? guard : -guard;
                if (i < MK - 1) cp[i] = sbeta[i] / m;
                y[i] = (y[i] - sbeta[i - 1] * y[i - 1]) / m;
            }
            for (int i = MK - 2; i >= 0; i--) y[i] -= cp[i] * y[i + 1];
            double nn = 0.0;
            for (int i = 0; i < MK; i++) nn += y[i] * y[i];
            double inv = 1.0 / sqrt(nn);
            for (int i = 0; i < MK; i++) y[i] *= inv;
        }
    }
    __syncthreads();

    // ---- lift: U16[:,t] = Q * y_t (fp64 accumulate) ----
    for (int t = 0; t < NR; t++) {
        double s = 0.0;
        const float* qr = &Q[tid * APQ];
        for (int k = 0; k < MK; k++) s += (double)qr[k] * Ytr[t][k];
        U16[tid * APR + t] = s;
    }
    __syncthreads();

    // ---- fp64 MGS orthonormalization ----
    for (int a = 0; a < NR; a++) {
        double va = U16[tid * APR + a];
        double nn = bsum128d(va * va, r4d);
        double inv = 1.0 / sqrt(fmax(nn, 1e-300));
        va *= inv;
        U16[tid * APR + a] = va;
        for (int b = a + 1; b < NR; b++) {
            double d = bsum128d(va * U16[tid * APR + b], r4d);
            U16[tid * APR + b] -= d * va;
        }
    }

    // ---- W16 = G(fp64) * U16 ----
    {
        double acc[NR];
#pragma unroll
        for (int t = 0; t < NR; t++) acc[t] = 0.0;
        const double* gr = Gd + (size_t)tid * LW;
        for (int l = 0; l < LW; l++) {
            double g = gr[l];
            const double* ur = &U16[l * APR];
#pragma unroll
            for (int t = 0; t < NR; t++) acc[t] += g * ur[t];
        }
#pragma unroll
        for (int t = 0; t < NR; t++) W16[tid * APR + t] = acc[t];
    }
    __syncthreads();

    // ---- H16 = U16^T W16 (fp64), symmetrized ----
    for (int e = tid; e < NR * NR; e += 128) {
        int a = e >> 4, b = e & 15;
        if (a <= b) {
            double s = 0;
            for (int i = 0; i < LW; i++) s += U16[i * APR + a] * W16[i * APR + b];
            H16[a * APR + b] = s;
            H16[b * APR + a] = s;
        }
    }
    for (int e = tid; e < NR * NR; e += 128) {
        int a = e >> 4, b = e & 15;
        Z16[a * APR + b] = (a == b) ? 1.0 : 0.0;
    }
    __syncthreads();

    // ---- 16x16 fp64 Jacobi, 4 fixed sweeps ----
    for (int sweep = 0; sweep < 4; sweep++) {
        for (int r = 0; r < NR - 1; r++) {
            if (tid < 8) {
                int p, q;
                if (tid == 0) { p = NR - 1; q = r; }
                else { p = (r + tid) % (NR - 1); q = (r + NR - 1 - tid) % (NR - 1); }
                double app = H16[p * APR + p], aqq = H16[q * APR + q], apq = H16[p * APR + q];
                double c = 1.0, s = 0.0;
                if (fabs(apq) > 0.0) {
                    double th = (aqq - app) / (2.0 * apq);
                    double t = ((th >= 0.0) ? 1.0 : -1.0) /
                               (fabs(th) + sqrt(1.0 + th * th));
                    c = 1.0 / sqrt(1.0 + t * t);
                    s = t * c;
                }
                sp[tid] = p; sq[tid] = q; dc8[tid] = c; ds8[tid] = s;
            }
            __syncthreads();
            if (tid < 8 * NR) {
                int pr = tid >> 4, jj = tid & 15;
                int p = sp[pr], q = sq[pr];
                double c = dc8[pr], s = ds8[pr];
                double ap = H16[p * APR + jj], aq = H16[q * APR + jj];
                H16[p * APR + jj] = c * ap - s * aq;
                H16[q * APR + jj] = s * ap + c * aq;
            }
            __syncthreads();
            if (tid < 8 * NR) {
                int pr = tid >> 4, rr = tid & 15;
                int p = sp[pr], q = sq[pr];
                double c = dc8[pr], s = ds8[pr];
                double ap = H16[rr * APR + p], aq = H16[rr * APR + q];
                H16[rr * APR + p] = c * ap - s * aq;
                H16[rr * APR + q] = s * ap + c * aq;
                double zp = Z16[rr * APR + p], zq = Z16[rr * APR + q];
                Z16[rr * APR + p] = c * zp - s * zq;
                Z16[rr * APR + q] = s * zp + c * zq;
            }
            __syncthreads();
        }
    }

    // ---- top-4 refined eigenpairs, project back ----
    if (tid == 0) {
        double ev[NR];
        for (int a = 0; a < NR; a++) ev[a] = H16[a * APR + a];
        for (int j = 0; j < 4; j++) {
            int bi = 0;
            double bv = -1e300;
            for (int a = 0; a < NR; a++)
                if (ev[a] > bv) { bv = ev[a]; bi = a; }
            idx4[j] = bi;
            ev[bi] = -1e300;
        }
    }
    __syncthreads();
    for (int j = 0; j < 4; j++) {
        double s = 0;
#pragma unroll
        for (int a = 0; a < NR; a++) s += U16[tid * APR + a] * Z16[a * APR + idx4[j]];
        g_V4[(bc * DCOMP + j) * LW + tid] = (float)s;
    }
}

// ---------------------------------------------------------------------------
// Kernel 3: reconstruction.
// ---------------------------------------------------------------------------
__global__ void recon_kernel(const float* __restrict__ x, float* __restrict__ out) {
    __shared__ float xs[NLEN];
    __shared__ float vv[LW];
    __shared__ float w[KK];
    int bc = blockIdx.x;
    int comp = blockIdx.y;
    const float* xp = x + bc * NLEN;
    for (int i = threadIdx.x; i < NLEN; i += 256) xs[i] = xp[i];
    if (threadIdx.x < LW)
        vv[threadIdx.x] = g_V4[(bc * DCOMP + comp) * LW + threadIdx.x];
    __syncthreads();

    for (int k = threadIdx.x; k < KK; k += 256) {
        float a = 0.0f;
#pragma unroll 8
        for (int l = 0; l < LW; l++) a += xs[k + l] * vv[l];
        w[k] = a;
    }
    __syncthreads();

    float* op = out + ((size_t)comp * NCH + bc) * NLEN;
    for (int n = threadIdx.x; n < NLEN; n += 256) {
        int lmin = (n > KK - 1) ? (n - (KK - 1)) : 0;
        int lmax = (n < LW - 1) ? n : (LW - 1);
        float a = 0.0f;
        for (int l = lmin; l <= lmax; l++) a += vv[l] * w[n - l];
        int cnt = min(min(n + 1, NLEN - n), LW);
        op[n] = a / (float)cnt;
    }
}

// ---------------------------------------------------------------------------
extern "C" void kernel_launch(void* const* d_in, const int* in_sizes, int n_in,
                              void* d_out, int out_size) {
    const float* x = (const float*)d_in[0];
    float* out = (float*)d_out;

    const int SMEME = (LW * APG + LW * APQ) * (int)sizeof(float)
                      + 2 * LW * APR * (int)sizeof(double);  // 134144 B
    cudaFuncSetAttribute(eigen_kernel, cudaFuncAttributeMaxDynamicSharedMemorySize, SMEME);

    gram_kernel<<<NCH, 128>>>(x);
    eigen_kernel<<<NCH, 128, SMEME>>>();
    recon_kernel<<<dim3(NCH, DCOMP), 256>>>(x, out);
}

// round 5
// speedup vs baseline: 21.2780x; 1.4898x over previous
#include <cuda_runtime.h>
#include <math.h>

#define NCH   64
#define NLEN  2048
#define LW    128
#define KK    1921
#define DCOMP 4

#define MK    48     // Krylov dimension
#define APG   129    // fp32 G smem pitch
#define APQ   49     // Q smem pitch (MK+1, odd)
#define NR    16     // refined subspace size
#define APR   17     // U16/W16 pitch (doubles)

__device__ double g_G[NCH * LW * LW];             // fp64 Gram matrices
__device__ float  g_V4[NCH * LW * DCOMP];         // top-4 eigenvectors, interleaved per l

// ---------------------------------------------------------------------------
__device__ __forceinline__ float bsum128f(float v, volatile float* r8) {
#pragma unroll
    for (int o = 16; o; o >>= 1) v += __shfl_xor_sync(0xffffffffu, v, o);
    if ((threadIdx.x & 31) == 0) r8[threadIdx.x >> 5] = v;
    __syncthreads();
    float s = r8[0] + r8[1] + r8[2] + r8[3];
    __syncthreads();
    return s;
}
__device__ __forceinline__ float2 bsum128f2(float a, float b, volatile float* r8) {
#pragma unroll
    for (int o = 16; o; o >>= 1) {
        a += __shfl_xor_sync(0xffffffffu, a, o);
        b += __shfl_xor_sync(0xffffffffu, b, o);
    }
    if ((threadIdx.x & 31) == 0) {
        r8[threadIdx.x >> 5] = a;
        r8[4 + (threadIdx.x >> 5)] = b;
    }
    __syncthreads();
    float2 out = make_float2(r8[0] + r8[1] + r8[2] + r8[3],
                             r8[4] + r8[5] + r8[6] + r8[7]);
    __syncthreads();
    return out;
}

// ---------------------------------------------------------------------------
// Fused kernel: Gram (fp32 prod / fp64 chunk-accum) -> Lanczos (fp32, CGS2)
//   -> parallel fp32 bisection -> fp64 inverse iteration -> fused fp64 MGS
//   -> fp64 Rayleigh-Ritz refinement -> top-4 eigenvectors.
// One CTA (128 threads) per channel.
// ---------------------------------------------------------------------------
__global__ void __launch_bounds__(128, 1) eigen_kernel(const float* __restrict__ x) {
    extern __shared__ char smraw[];
    float*  G32 = (float*)smraw;                 // 128*129 f32
    float*  Q   = G32 + LW * APG;                // 128*49  f32
    double* U16 = (double*)(Q + LW * APQ);       // 128*17  f64
    double* W16 = U16 + LW * APR;                // 128*17  f64
    float*  xs  = (float*)W16;                   // overlay (gram stage only)

    __shared__ double cd[LW];
    __shared__ float  u[LW];
    __shared__ float  cvec[MK];
    __shared__ float  r8f[8];
    __shared__ double dred[4][NR];
    __shared__ double salpha[MK];
    __shared__ double sbeta[MK];
    __shared__ float  sa32[MK];
    __shared__ float  sb232[MK];
    __shared__ double Ytr[NR][MK];
    __shared__ double cpw[NR][MK];
    __shared__ double lam[NR];
    __shared__ double H16[NR * APR];
    __shared__ double Z16[NR * APR];
    __shared__ int    sp[8], sq[8];
    __shared__ double dc8[8], ds8[8];
    __shared__ int    idx4[4];

    int tid = threadIdx.x;
    int lane = tid & 31, wid = tid >> 5;
    int bc = blockIdx.x;
    double* Gd = g_G + (size_t)bc * LW * LW;

    // ================= Gram stage =================
    {
        const float* xp = x + bc * NLEN;
        for (int i = tid; i < NLEN; i += 128) xs[i] = xp[i];
        __syncthreads();

        // first row: fp32 products, fp64 accumulation every 32
        int m = tid;
        double dacc = 0.0;
        for (int chunk = 0; chunk < KK; chunk += 32) {
            float f = 0.f;
            int kend = (chunk + 32 < KK) ? chunk + 32 : KK;
            for (int k = chunk; k < kend; k++) f = fmaf(xs[k], xs[k + m], f);
            dacc += (double)f;
        }
        cd[m] = dacc;
        __syncthreads();

        // Hankel diagonal recurrence (fp32 delta, fp64 carry)
        int dg = tid;
        double g = cd[dg];
        Gd[dg] = g;
        Gd[dg * LW] = g;
        G32[dg] = (float)g;
        G32[dg * APG] = (float)g;
        for (int l = 1; l < LW - dg; l++) {
            int mm = l + dg;
            float delta = fmaf(xs[KK + l - 1], xs[KK + mm - 1],
                               -xs[l - 1] * xs[mm - 1]);
            g += (double)delta;
            float gf = (float)g;
            G32[l * APG + mm] = gf;
            G32[mm * APG + l] = gf;
            Gd[l * LW + mm] = g;
            Gd[mm * LW + l] = g;
        }
        __syncthreads();
    }

    // ================= Lanczos (fp32, CGS2) =================
    {
        float q0 = 1.0f + 0.5f * __sinf(0.7f * (float)tid + 0.3f);
        float n2 = bsum128f(q0 * q0, r8f);
        Q[tid * APQ + 0] = q0 * rsqrtf(n2);
        __syncthreads();
    }

    for (int j = 0; j < MK; j++) {
        float a0 = 0, a1 = 0, a2 = 0, a3 = 0;
        const float* gr = &G32[tid * APG];
        for (int l = 0; l < LW; l += 4) {
            a0 += gr[l]     * Q[l * APQ + j];
            a1 += gr[l + 1] * Q[(l + 1) * APQ + j];
            a2 += gr[l + 2] * Q[(l + 2) * APQ + j];
            a3 += gr[l + 3] * Q[(l + 3) * APQ + j];
        }
        float uv = (a0 + a1) + (a2 + a3);
        u[tid] = uv;
        __syncthreads();

        float2 an = bsum128f2(Q[tid * APQ + j] * uv, uv * uv, r8f);
        if (tid == 0) salpha[j] = (double)an.x;
        if (j == MK - 1) break;
        float pre2 = an.y;

        for (int pass = 0; pass < 2; pass++) {
            for (int t = wid; t <= j; t += 4) {
                float s = 0;
#pragma unroll
                for (int i = lane; i < LW; i += 32) s += Q[i * APQ + t] * u[i];
#pragma unroll
                for (int o = 16; o; o >>= 1) s += __shfl_xor_sync(0xffffffffu, s, o);
                if (lane == 0) cvec[t] = s;
            }
            __syncthreads();
            float corr = 0;
            for (int t = 0; t <= j; t++) corr += Q[tid * APQ + t] * cvec[t];
            u[tid] -= corr;
            __syncthreads();
        }
        float b2 = bsum128f(u[tid] * u[tid], r8f);
        float bn = sqrtf(fmaxf(b2, pre2 * 1e-14f + 1e-30f));
        if (tid == 0) sbeta[j] = (double)bn;
        Q[tid * APQ + (j + 1)] = u[tid] / bn;
        __syncthreads();
    }
    __syncthreads();

    if (tid < MK) sa32[tid] = (float)salpha[tid];
    if (tid < MK - 1) sb232[tid] = (float)(sbeta[tid] * sbeta[tid]);
    __syncthreads();

    // ================= parallel fp32 bisection (8 thr/eig, 9-way) ==========
    {
        int g = tid >> 3, sub = tid & 7;
        int p = MK - 1 - g;
        float lo = 3e38f, hi = -3e38f, bmax = 0.f;
        for (int i = 0; i < MK; i++) {
            float bl = (i > 0) ? sqrtf(sb232[i - 1]) : 0.f;
            float br = (i < MK - 1) ? sqrtf(sb232[i]) : 0.f;
            float r = bl + br;
            lo = fminf(lo, sa32[i] - r);
            hi = fmaxf(hi, sa32[i] + r);
            bmax = fmaxf(bmax, fmaxf(fabsf(sa32[i]), br));
        }
        float gguard = bmax * 1e-6f + 1e-30f;

        for (int round = 0; round < 8; round++) {
            float w = hi - lo;
            float mid = lo + w * (float)(sub + 1) * (1.0f / 9.0f);
            int cnt = 0;
            float d = 1.0f;
            for (int i = 0; i < MK; i++) {
                float off = (i > 0) ? __fdividef(sb232[i - 1], d) : 0.f;
                d = sa32[i] - mid - off;
                cnt += (d < 0.f);
                if (fabsf(d) < gguard) d = -gguard;
            }
            float clo = (cnt <= p) ? mid : lo;
            float chi = (cnt > p) ? mid : hi;
#pragma unroll
            for (int o = 4; o; o >>= 1) {
                clo = fmaxf(clo, __shfl_xor_sync(0xffffffffu, clo, o));
                chi = fminf(chi, __shfl_xor_sync(0xffffffffu, chi, o));
            }
            lo = clo;
            hi = chi;
        }
        if (sub == 0) lam[g] = 0.5 * ((double)lo + (double)hi);
    }
    __syncthreads();

    // ================= fp64 inverse iteration (16 threads) =================
    if (tid < NR) {
        double bmaxd = 0.0;
        for (int i = 0; i < MK; i++) {
            double br = (i < MK - 1) ? fabs(sbeta[i]) : 0.0;
            bmaxd = fmax(bmaxd, fmax(fabs(salpha[i]), br));
        }
        double guard = bmaxd * 1e-13 + 1e-300;
        double lv = lam[tid];
        double* y = Ytr[tid];
        double* cp = cpw[tid];
        for (int i = 0; i < MK; i++)
            y[i] = (double)__sinf(0.613f * (float)((i + 2) * (tid + 5)) + 0.21f);
        for (int iter = 0; iter < 2; iter++) {
            double d = salpha[0] - lv;
            if (fabs(d) < guard) d = (d >= 0) ? guard : -guard;
            cp[0] = sbeta[0] / d;
            y[0] = y[0] / d;
            for (int i = 1; i < MK; i++) {
                double mdiag = salpha[i] - lv - sbeta[i - 1] * cp[i - 1];
                if (fabs(mdiag) < guard) mdiag = (mdiag >= 0) ? guard : -guard;
                if (i < MK - 1) cp[i] = sbeta[i] / mdiag;
                y[i] = (y[i] - sbeta[i - 1] * y[i - 1]) / mdiag;
            }
            for (int i = MK - 2; i >= 0; i--) y[i] -= cp[i] * y[i + 1];
            double nn = 0.0;
            for (int i = 0; i < MK; i++) nn += y[i] * y[i];
            double inv = 1.0 / sqrt(nn);
            for (int i = 0; i < MK; i++) y[i] *= inv;
        }
    }
    __syncthreads();

    // ================= lift U16 = Q * Ytr (fp64 accumulate) =================
    for (int t = 0; t < NR; t++) {
        double s = 0.0;
        const float* qr = &Q[tid * APQ];
        for (int k = 0; k < MK; k++) s += (double)qr[k] * Ytr[t][k];
        U16[tid * APR + t] = s;
    }
    __syncthreads();

    // ================= fused-batch fp64 MGS =================
    for (int a = 0; a < NR; a++) {
        double va = U16[tid * APR + a];
        double dv[NR];
#pragma unroll
        for (int b = 0; b < NR; b++)
            dv[b] = (b >= a) ? va * U16[tid * APR + b] : 0.0;
#pragma unroll
        for (int o = 16; o; o >>= 1)
#pragma unroll
            for (int b = 0; b < NR; b++)
                dv[b] += __shfl_xor_sync(0xffffffffu, dv[b], o);
        if (lane == 0)
#pragma unroll
            for (int b = 0; b < NR; b++) dred[wid][b] = dv[b];
        __syncthreads();
        double nn = dred[0][a] + dred[1][a] + dred[2][a] + dred[3][a];
        double innn = 1.0 / fmax(nn, 1e-300);
        double inv = sqrt(innn);
        for (int b = a + 1; b < NR; b++) {
            double tot = dred[0][b] + dred[1][b] + dred[2][b] + dred[3][b];
            U16[tid * APR + b] -= (tot * innn) * va;
        }
        U16[tid * APR + a] = va * inv;
        __syncthreads();
    }

    // ================= W16 = G(fp64) * U16 =================
    {
        double acc[NR];
#pragma unroll
        for (int t = 0; t < NR; t++) acc[t] = 0.0;
        const double* gr = Gd + (size_t)tid * LW;
        for (int l = 0; l < LW; l++) {
            double g = gr[l];
            const double* ur = &U16[l * APR];
#pragma unroll
            for (int t = 0; t < NR; t++) acc[t] += g * ur[t];
        }
#pragma unroll
        for (int t = 0; t < NR; t++) W16[tid * APR + t] = acc[t];
    }
    __syncthreads();

    // ================= H16 = U16^T W16, symmetrized =================
    for (int e = tid; e < NR * NR; e += 128) {
        int a = e >> 4, b = e & 15;
        if (a <= b) {
            double s = 0;
            for (int i = 0; i < LW; i++) s += U16[i * APR + a] * W16[i * APR + b];
            H16[a * APR + b] = s;
            H16[b * APR + a] = s;
        }
    }
    for (int e = tid; e < NR * NR; e += 128) {
        int a = e >> 4, b = e & 15;
        Z16[a * APR + b] = (a == b) ? 1.0 : 0.0;
    }
    __syncthreads();

    // ================= 16x16 fp64 Jacobi, 4 sweeps =================
    for (int sweep = 0; sweep < 4; sweep++) {
        for (int r = 0; r < NR - 1; r++) {
            if (tid < 8) {
                int p, q;
                if (tid == 0) { p = NR - 1; q = r; }
                else { p = (r + tid) % (NR - 1); q = (r + NR - 1 - tid) % (NR - 1); }
                double app = H16[p * APR + p], aqq = H16[q * APR + q], apq = H16[p * APR + q];
                double c = 1.0, s = 0.0;
                if (fabs(apq) > 0.0) {
                    double th = (aqq - app) / (2.0 * apq);
                    double t = ((th >= 0.0) ? 1.0 : -1.0) /
                               (fabs(th) + sqrt(1.0 + th * th));
                    c = 1.0 / sqrt(1.0 + t * t);
                    s = t * c;
                }
                sp[tid] = p; sq[tid] = q; dc8[tid] = c; ds8[tid] = s;
            }
            __syncthreads();
            if (tid < 8 * NR) {
                int pr = tid >> 4, jj = tid & 15;
                int p = sp[pr], q = sq[pr];
                double c = dc8[pr], s = ds8[pr];
                double ap = H16[p * APR + jj], aq = H16[q * APR + jj];
                H16[p * APR + jj] = c * ap - s * aq;
                H16[q * APR + jj] = s * ap + c * aq;
            }
            __syncthreads();
            if (tid < 8 * NR) {
                int pr = tid >> 4, rr = tid & 15;
                int p = sp[pr], q = sq[pr];
                double c = dc8[pr], s = ds8[pr];
                double ap = H16[rr * APR + p], aq = H16[rr * APR + q];
                H16[rr * APR + p] = c * ap - s * aq;
                H16[rr * APR + q] = s * ap + c * aq;
                double zp = Z16[rr * APR + p], zq = Z16[rr * APR + q];
                Z16[rr * APR + p] = c * zp - s * zq;
                Z16[rr * APR + q] = s * zp + c * zq;
            }
            __syncthreads();
        }
    }

    // ================= top-4, project back (interleaved layout) ============
    if (tid == 0) {
        double ev[NR];
        for (int a = 0; a < NR; a++) ev[a] = H16[a * APR + a];
        for (int j = 0; j < 4; j++) {
            int bi = 0;
            double bv = -1e300;
            for (int a = 0; a < NR; a++)
                if (ev[a] > bv) { bv = ev[a]; bi = a; }
            idx4[j] = bi;
            ev[bi] = -1e300;
        }
    }
    __syncthreads();
    {
        float vout[4];
#pragma unroll
        for (int j = 0; j < 4; j++) {
            double s = 0;
#pragma unroll
            for (int a = 0; a < NR; a++)
                s += U16[tid * APR + a] * Z16[a * APR + idx4[j]];
            vout[j] = (float)s;
        }
        *(float4*)&g_V4[(bc * LW + tid) * DCOMP] =
            make_float4(vout[0], vout[1], vout[2], vout[3]);
    }
}

// ---------------------------------------------------------------------------
// Recon: w = T v (4-wide sliding window), conv(w, v) with zero-padded w.
// grid (NCH, DCOMP), 256 threads.
// ---------------------------------------------------------------------------
__global__ void __launch_bounds__(256) recon_kernel(const float* __restrict__ x,
                                                    float* __restrict__ out) {
    __shared__ float xs[NLEN + 8];
    __shared__ float vv[LW];
    __shared__ float wp[127 + KK + 127];   // 2175, zero-padded both sides
    int bc = blockIdx.x;
    int comp = blockIdx.y;
    int tid = threadIdx.x;

    const float* xp = x + bc * NLEN;
    for (int i = tid; i < NLEN; i += 256) xs[i] = xp[i];
    if (tid < 8) xs[NLEN + tid] = 0.f;
    if (tid < LW) vv[tid] = g_V4[(bc * LW + tid) * DCOMP + comp];
    for (int i = tid; i < 127 + KK + 127; i += 256) wp[i] = 0.f;
    __syncthreads();

    // stage 1: w[k] = sum_l xs[k+l] vv[l], 4 outputs per thread-group
    for (int grp = tid; grp <= 480; grp += 256) {
        int k0 = grp * 4;
        float w0 = xs[k0], w1 = xs[k0 + 1], w2 = xs[k0 + 2];
        float a0 = 0, a1 = 0, a2 = 0, a3 = 0;
#pragma unroll 4
        for (int l = 0; l < LW; l++) {
            float w3 = xs[k0 + l + 3];
            float v = vv[l];
            a0 = fmaf(w0, v, a0);
            a1 = fmaf(w1, v, a1);
            a2 = fmaf(w2, v, a2);
            a3 = fmaf(w3, v, a3);
            w0 = w1; w1 = w2; w2 = w3;
        }
        wp[127 + k0] = a0;
        if (k0 + 3 < KK) {
            wp[128 + k0] = a1;
            wp[129 + k0] = a2;
            wp[130 + k0] = a3;
        }
    }
    __syncthreads();

    // stage 2: out[n] = (sum_l vv[l] wp[127+n-l]) / cnt
    float* op = out + ((size_t)comp * NCH + bc) * NLEN;
    for (int grp = tid; grp < 512; grp += 256) {
        int n0 = grp * 4;
        float r1 = wp[128 + n0], r2 = wp[129 + n0], r3 = wp[130 + n0];
        float a0 = 0, a1 = 0, a2 = 0, a3 = 0;
#pragma unroll 4
        for (int l = 0; l < LW; l++) {
            float r0 = wp[127 + n0 - l];
            float v = vv[l];
            a0 = fmaf(v, r0, a0);
            a1 = fmaf(v, r1, a1);
            a2 = fmaf(v, r2, a2);
            a3 = fmaf(v, r3, a3);
            r3 = r2; r2 = r1; r1 = r0;
        }
#pragma unroll
        for (int j = 0; j < 4; j++) {
            int n = n0 + j;
            int cnt = min(min(n + 1, NLEN - n), LW);
            float a = (j == 0) ? a0 : (j == 1) ? a1 : (j == 2) ? a2 : a3;
            op[n] = a / (float)cnt;
        }
    }
}

// ---------------------------------------------------------------------------
extern "C" void kernel_launch(void* const* d_in, const int* in_sizes, int n_in,
                              void* d_out, int out_size) {
    const float* x = (const float*)d_in[0];
    float* out = (float*)d_out;

    const int SMEME = (LW * APG + LW * APQ) * (int)sizeof(float)
                      + 2 * LW * APR * (int)sizeof(double);  // 125952 B
    cudaFuncSetAttribute(eigen_kernel, cudaFuncAttributeMaxDynamicSharedMemorySize, SMEME);

    eigen_kernel<<<NCH, 128, SMEME>>>(x);
    recon_kernel<<<dim3(NCH, DCOMP), 256>>>(x, out);
}